// round 6
// baseline (speedup 1.0000x reference)
#include <cuda_runtime.h>
#include <cuda_bf16.h>
#include <math.h>

// ---------------------------------------------------------------------------
// Problem dims (fixed)
// ---------------------------------------------------------------------------
#define T_   2048
#define D_   1024
#define H_   16
#define HD_  64
#define NH_  2
#define STEPS (T_*NH_)          // 4096
#define ROW  (H_*HD_)           // 1024
#define SPAD (STEPS + 8)        // padded step count (prefetch overrun)
#define GSTEPS 8
#define NGRP8 (STEPS/GSTEPS)    // 512 groups of 8 steps

// ---------------------------------------------------------------------------
// Scratch (static device memory; allocation-free).
// ---------------------------------------------------------------------------
__device__ __align__(256) float g_qbuf[(T_ + 4) * ROW];
__device__ __align__(256) float g_kbuf[SPAD * ROW];
__device__ __align__(256) float g_vbuf[SPAD * ROW];
__device__ __align__(256) float g_gbuf[T_ * ROW];
__device__ __align__(256) float g_bbuf[T_ * (NH_ * H_)];
__device__ __align__(256) float g_abuf[T_ * H_];
__device__ __align__(256) float g_betab[H_ * SPAD];     // transposed [h][s]
__device__ __align__(256) float g_decb[H_ * SPAD];      // transposed [h][s]
__device__ __align__(256) float g_obuf[T_ * ROW];

// ---------------------------------------------------------------------------
// f32x2 packed helpers (FFMA2 path: 2x fp32 throughput, PTX-only)
// ---------------------------------------------------------------------------
typedef unsigned long long ull;

__device__ __forceinline__ void fma2(ull& d, ull a, ull b) {
    asm("fma.rn.f32x2 %0, %1, %2, %3;" : "=l"(d) : "l"(a), "l"(b), "l"(d));
}
__device__ __forceinline__ void add2(ull& d, ull a, ull b) {
    asm("add.rn.f32x2 %0, %1, %2;" : "=l"(d) : "l"(a), "l"(b));
}
__device__ __forceinline__ ull mul2(ull a, ull b) {
    ull d;
    asm("mul.rn.f32x2 %0, %1, %2;" : "=l"(d) : "l"(a), "l"(b));
    return d;
}
__device__ __forceinline__ ull pk2(float x, float y) {
    ull r;
    asm("mov.b64 %0, {%1, %2};" : "=l"(r)
        : "r"(__float_as_uint(x)), "r"(__float_as_uint(y)));
    return r;
}
__device__ __forceinline__ void up2(ull v, float& lo, float& hi) {
    unsigned a, b;
    asm("mov.b64 {%0, %1}, %2;" : "=r"(a), "=r"(b) : "l"(v));
    lo = __uint_as_float(a); hi = __uint_as_float(b);
}

// ---------------------------------------------------------------------------
// cp.async helpers (cpasync16 copies 16 BYTES = 4 floats)
// ---------------------------------------------------------------------------
__device__ __forceinline__ void cpasync16(void* dst, const void* src) {
    unsigned d = (unsigned)__cvta_generic_to_shared(dst);
    asm volatile("cp.async.cg.shared.global [%0], [%1], 16;" :: "r"(d), "l"(src));
}
#define CP_COMMIT() asm volatile("cp.async.commit_group;")
#define CP_WAIT(n)  asm volatile("cp.async.wait_group %0;" :: "n"(n))

// ---------------------------------------------------------------------------
// Big SGEMM: C[M,N] = A[M,K] @ B[K,N], row-major fp32, FFMA2.
// 128x128 tile, BK=16, 256 threads (8 warps = 2/SMSP), 8x8 microtile
// (4 ull row-pairs x 8 cols). M%128==0, N%128==0, K%16==0.
// ---------------------------------------------------------------------------
#define GBK 16

__global__ void __launch_bounds__(256) sgemm_big_kernel(
    const float* __restrict__ A, const float* __restrict__ B,
    float* __restrict__ C, int M, int N, int K)
{
    __shared__ float As[2][GBK][128];   // [buf][k][row]
    __shared__ float Bs[2][GBK][128];   // [buf][k][col]

    const int tid = threadIdx.x;
    const int tx = tid & 15;            // 8 cols each
    const int ty = tid >> 4;            // 8 rows each
    const int rowC = blockIdx.y * 128;
    const int colC = blockIdx.x * 128;

    const int rowA = tid >> 1;          // 0..127
    const int kA   = (tid & 1) * 8;     // 0 or 8
    const int rowB = tid >> 4;          // 0..15
    const int colB = (tid & 15) * 8;    // 0..120

    const float* Ap = A + (size_t)(rowC + rowA) * K + kA;
    const float* Bp = B + (size_t)rowB * N + colC + colB;

    ull acc[4][8];
#pragma unroll
    for (int r = 0; r < 4; r++)
#pragma unroll
        for (int c = 0; c < 8; c++) acc[r][c] = 0ull;

    const int nt = K / GBK;

    // prologue: fill buffer 0
    {
        float4 a0 = *(const float4*)(Ap + 0);
        float4 a1 = *(const float4*)(Ap + 4);
        As[0][kA + 0][rowA] = a0.x; As[0][kA + 1][rowA] = a0.y;
        As[0][kA + 2][rowA] = a0.z; As[0][kA + 3][rowA] = a0.w;
        As[0][kA + 4][rowA] = a1.x; As[0][kA + 5][rowA] = a1.y;
        As[0][kA + 6][rowA] = a1.z; As[0][kA + 7][rowA] = a1.w;
        cpasync16(&Bs[0][rowB][colB + 0], Bp + 0);
        cpasync16(&Bs[0][rowB][colB + 4], Bp + 4);
        CP_COMMIT();
        CP_WAIT(0);
    }
    __syncthreads();

    for (int t = 0; t < nt; t++) {
        const int cur = t & 1;
        const int nxt = cur ^ 1;

        if (t + 1 < nt) {
            const int k0 = (t + 1) * GBK;
            float4 a0 = *(const float4*)(Ap + k0 + 0);
            float4 a1 = *(const float4*)(Ap + k0 + 4);
            const float* bsrc = Bp + (size_t)k0 * N;
            cpasync16(&Bs[nxt][rowB][colB + 0], bsrc + 0);
            cpasync16(&Bs[nxt][rowB][colB + 4], bsrc + 4);
            CP_COMMIT();
            As[nxt][kA + 0][rowA] = a0.x; As[nxt][kA + 1][rowA] = a0.y;
            As[nxt][kA + 2][rowA] = a0.z; As[nxt][kA + 3][rowA] = a0.w;
            As[nxt][kA + 4][rowA] = a1.x; As[nxt][kA + 5][rowA] = a1.y;
            As[nxt][kA + 6][rowA] = a1.z; As[nxt][kA + 7][rowA] = a1.w;
        } else {
            CP_COMMIT();
        }

#pragma unroll
        for (int kk = 0; kk < GBK; kk++) {
            ull a2r[4];
#pragma unroll
            for (int r = 0; r < 4; r++)
                a2r[r] = *(const ull*)&As[cur][kk][ty * 8 + 2 * r];
            float4 b0 = *(const float4*)&Bs[cur][kk][tx * 8];
            float4 b1 = *(const float4*)&Bs[cur][kk][tx * 8 + 4];
            ull b2[8];
            b2[0] = pk2(b0.x, b0.x); b2[1] = pk2(b0.y, b0.y);
            b2[2] = pk2(b0.z, b0.z); b2[3] = pk2(b0.w, b0.w);
            b2[4] = pk2(b1.x, b1.x); b2[5] = pk2(b1.y, b1.y);
            b2[6] = pk2(b1.z, b1.z); b2[7] = pk2(b1.w, b1.w);
#pragma unroll
            for (int r = 0; r < 4; r++)
#pragma unroll
                for (int c = 0; c < 8; c++)
                    fma2(acc[r][c], a2r[r], b2[c]);
        }

        CP_WAIT(0);
        __syncthreads();
    }

    // epilogue: 8x8 microtile as 4 row-pairs
#pragma unroll
    for (int r = 0; r < 4; r++) {
        float lo[8], hi[8];
#pragma unroll
        for (int c = 0; c < 8; c++) up2(acc[r][c], lo[c], hi[c]);
        int row0 = rowC + ty * 8 + 2 * r;
        float* c0 = C + (size_t)row0 * N + colC + tx * 8;
        float* c1 = c0 + N;
        *(float4*)(c0 + 0) = make_float4(lo[0], lo[1], lo[2], lo[3]);
        *(float4*)(c0 + 4) = make_float4(lo[4], lo[5], lo[6], lo[7]);
        *(float4*)(c1 + 0) = make_float4(hi[0], hi[1], hi[2], hi[3]);
        *(float4*)(c1 + 4) = make_float4(hi[4], hi[5], hi[6], hi[7]);
    }
}

// ---------------------------------------------------------------------------
// Small SGEMM (N=16/32): 128x64 tile, BK=16, 256 threads.
// ---------------------------------------------------------------------------
#define BM 128
#define BN 64
#define BK 16

__global__ void __launch_bounds__(256) sgemm_kernel(
    const float* __restrict__ A, const float* __restrict__ B,
    float* __restrict__ C, int M, int N, int K)
{
    __shared__ float As[BK][BM + 4];
    __shared__ float Bs[BK][BN];

    const int tid = threadIdx.x;
    const int tx = tid & 15;
    const int ty = tid >> 4;
    const int rowC = blockIdx.y * BM;
    const int colC = blockIdx.x * BN;

    const int rowA = tid >> 2;
    const int kA   = (tid & 3) * 4;
    const int rowB = tid >> 4;
    const int colB = (tid & 15) * 4;

    ull acc2[4][4];
#pragma unroll
    for (int r = 0; r < 4; r++)
#pragma unroll
        for (int jj = 0; jj < 4; jj++) acc2[r][jj] = 0ull;

    for (int k0 = 0; k0 < K; k0 += BK) {
#pragma unroll
        for (int r = 0; r < 2; r++) {
            int row = rowA + r * 64;
            float4 a = *(const float4*)(A + (size_t)(rowC + row) * K + k0 + kA);
            As[kA + 0][row] = a.x; As[kA + 1][row] = a.y;
            As[kA + 2][row] = a.z; As[kA + 3][row] = a.w;
        }
        {
            float4 bv = make_float4(0.f, 0.f, 0.f, 0.f);
            if (colC + colB < N)
                bv = *(const float4*)(B + (size_t)(k0 + rowB) * N + colC + colB);
            Bs[rowB][colB + 0] = bv.x; Bs[rowB][colB + 1] = bv.y;
            Bs[rowB][colB + 2] = bv.z; Bs[rowB][colB + 3] = bv.w;
        }
        __syncthreads();

#pragma unroll
        for (int kk = 0; kk < BK; kk++) {
            float4 b0 = *(const float4*)&Bs[kk][tx * 4];
            ull b2[4];
            b2[0] = pk2(b0.x, b0.x); b2[1] = pk2(b0.y, b0.y);
            b2[2] = pk2(b0.z, b0.z); b2[3] = pk2(b0.w, b0.w);
            ull a2[4];
#pragma unroll
            for (int r = 0; r < 4; r++)
                a2[r] = *(const ull*)&As[kk][ty * 8 + 2 * r];
#pragma unroll
            for (int r = 0; r < 4; r++)
#pragma unroll
                for (int jj = 0; jj < 4; jj++)
                    fma2(acc2[r][jj], a2[r], b2[jj]);
        }
        __syncthreads();
    }

    if (colC + tx * 4 < N) {
#pragma unroll
        for (int r = 0; r < 4; r++) {
            float lo[4], hi[4];
#pragma unroll
            for (int jj = 0; jj < 4; jj++) up2(acc2[r][jj], lo[jj], hi[jj]);
            int row0 = rowC + ty * 8 + 2 * r;
            *(float4*)(C + (size_t)row0 * N + colC + tx * 4) =
                make_float4(lo[0], lo[1], lo[2], lo[3]);
            *(float4*)(C + (size_t)(row0 + 1) * N + colC + tx * 4) =
                make_float4(hi[0], hi[1], hi[2], hi[3]);
        }
    }
}

// ---------------------------------------------------------------------------
// l2norm rows of 64 (q: scale by HD^-0.5; k: no scale). One warp per row.
// ---------------------------------------------------------------------------
__global__ void prep_norm_kernel()
{
    const int TQ = T_ * H_;
    const int TK = STEPS * H_;
    int w = (blockIdx.x * blockDim.x + threadIdx.x) >> 5;
    int lane = threadIdx.x & 31;
    if (w >= TQ + TK) return;
    float* p;
    float scl;
    if (w < TQ) { p = g_qbuf + (size_t)w * 64; scl = 0.125f; }
    else        { p = g_kbuf + (size_t)(w - TQ) * 64; scl = 1.0f; }
    float x0 = p[lane], x1 = p[lane + 32];
    float ss = x0 * x0 + x1 * x1;
#pragma unroll
    for (int o = 16; o; o >>= 1) ss += __shfl_xor_sync(0xffffffffu, ss, o);
    float rs = rsqrtf(ss + 1e-6f) * scl;
    p[lane] = x0 * rs;
    p[lane + 32] = x1 * rs;
}

// ---------------------------------------------------------------------------
// beta/dec precompute, written TRANSPOSED [h][s] for contiguous cp.async.
// ---------------------------------------------------------------------------
__global__ void prep_scalar_kernel(const float* __restrict__ A_log,
                                   const float* __restrict__ dt_bias)
{
    int i = blockIdx.x * blockDim.x + threadIdx.x;
    if (i >= STEPS * H_) return;
    int h = i & 15;
    int nh = (i >> 4) & 1;
    int t = i >> 5;
    int s = t * 2 + nh;
    float br = g_bbuf[i];
    g_betab[h * SPAD + s] = 2.0f / (1.0f + expf(-br));
    float d = 1.0f;
    if (nh == 0) {
        float a = g_abuf[t * H_ + h] + dt_bias[h];
        float sp = (a > 20.0f) ? a : log1pf(expf(a));
        d = expf(-expf(A_log[h]) * sp);
    }
    g_decb[h * SPAD + s] = d;
}

// ---------------------------------------------------------------------------
// Scan: cp.async smem ring (groups of 8, 4 slots, lookahead 3), f32x2 math.
// 32 blocks x 128 threads: block = (head, v-half), 4 threads/col x 16 rows
// = 8 ull pairs of state per thread.
// ---------------------------------------------------------------------------
__device__ __forceinline__ void scan_prefetch(
    int gi, int tid,
    const float* kg, const float* qg, const float* vg,
    const float* bg, const float* dg,
    float (*sk)[GSTEPS*64], float (*sq)[(GSTEPS/2)*64],
    float (*sv)[GSTEPS*32], float (*sb)[16])
{
    int slot = gi & 3;
    int s0 = gi * GSTEPS; if (s0 > STEPS) s0 = STEPS;
    int t0 = s0 >> 1;
    {   // k: 128 chunks
        int si = tid >> 4, off = (tid & 15) * 4;
        cpasync16(&sk[slot][si * 64 + off], kg + (size_t)(s0 + si) * ROW + off);
    }
    if (tid < 64) {   // q: 64 chunks
        int ti = tid >> 4, off = (tid & 15) * 4;
        cpasync16(&sq[slot][ti * 64 + off], qg + (size_t)(t0 + ti) * ROW + off);
    } else {          // v: 64 chunks
        int c = tid - 64; int si = c >> 3, off = (c & 7) * 4;
        cpasync16(&sv[slot][si * 32 + off], vg + (size_t)(s0 + si) * ROW + off);
    }
    if (tid < 2)      cpasync16(&sb[slot][tid * 4], bg + s0 + tid * 4);
    else if (tid < 4) cpasync16(&sb[slot][8 + (tid - 2) * 4], dg + s0 + (tid - 2) * 4);
}

__device__ __forceinline__ void lds8u(const float* p, ull* u)
{
    const ull* up = (const ull*)p;      // 8B-aligned (j*16 floats)
#pragma unroll
    for (int i = 0; i < 8; i++) u[i] = up[i];
}

__global__ void __launch_bounds__(128) scan_kernel()
{
    __shared__ float sk[4][GSTEPS*64];
    __shared__ float sq[4][(GSTEPS/2)*64];
    __shared__ float sv[4][GSTEPS*32];
    __shared__ float sb[4][16];           // [0..7]=beta, [8..15]=dec

    const int h = blockIdx.x >> 1;
    const int half = blockIdx.x & 1;
    const int tid = threadIdx.x;
    const int vloc = tid >> 2;
    const int j = tid & 3;
    const int v = (half << 5) + vloc;

    const float* kg = g_kbuf + h * 64;
    const float* qg = g_qbuf + h * 64;
    const float* vg = g_vbuf + h * 64 + half * 32;
    const float* bg = g_betab + h * SPAD;
    const float* dg = g_decb + h * SPAD;
    float* op = g_obuf + h * 64 + v;

    ull S2[8];
#pragma unroll
    for (int m = 0; m < 8; m++) S2[m] = 0ull;

    scan_prefetch(0, tid, kg, qg, vg, bg, dg, sk, sq, sv, sb); CP_COMMIT();
    scan_prefetch(1, tid, kg, qg, vg, bg, dg, sk, sq, sv, sb); CP_COMMIT();
    scan_prefetch(2, tid, kg, qg, vg, bg, dg, sk, sq, sv, sb); CP_COMMIT();
    CP_WAIT(2);
    __syncthreads();

    for (int g = 0; g < NGRP8; g++) {
        scan_prefetch(g + 3, tid, kg, qg, vg, bg, dg, sk, sq, sv, sb);
        CP_COMMIT();

        const int slot = g & 3;
        ull kc2[8], qc2[8];
        lds8u(&sk[slot][j * 16], kc2);

#pragma unroll
        for (int sp = 0; sp < GSTEPS; sp++) {
            const int s = g * GSTEPS + sp;
            ull kn2[8];
            if (sp < GSTEPS - 1) lds8u(&sk[slot][(sp + 1) * 64 + j * 16], kn2);
            if (!(sp & 1)) lds8u(&sq[slot][(sp >> 1) * 64 + j * 16], qc2);

            float vv = sv[slot][sp * 32 + vloc];
            float bb = sb[slot][sp];
            float dd = sb[slot][8 + sp];

            // pred = k . S  (packed, 4-way split)
            ull pa = 0ull, pb = 0ull, pc = 0ull, pd = 0ull;
            fma2(pa, kc2[0], S2[0]); fma2(pb, kc2[1], S2[1]);
            fma2(pc, kc2[2], S2[2]); fma2(pd, kc2[3], S2[3]);
            fma2(pa, kc2[4], S2[4]); fma2(pb, kc2[5], S2[5]);
            fma2(pc, kc2[6], S2[6]); fma2(pd, kc2[7], S2[7]);
            add2(pa, pa, pb); add2(pc, pc, pd); add2(pa, pa, pc);
            float plo, phi; up2(pa, plo, phi);
            float pred = plo + phi;
            pred += __shfl_xor_sync(0xffffffffu, pred, 1);
            pred += __shfl_xor_sync(0xffffffffu, pred, 2);

            float dv = (vv - dd * pred) * bb;
            ull dd2 = pk2(dd, dd);
            ull dv2 = pk2(dv, dv);
#pragma unroll
            for (int m = 0; m < 8; m++) {
                ull t = mul2(kc2[m], dv2);
                fma2(t, S2[m], dd2);          // t = S2*dd2 + kc2*dv2
                S2[m] = t;
            }

            if (sp & 1) {
                ull oa = 0ull, ob = 0ull, oc = 0ull, od = 0ull;
                fma2(oa, qc2[0], S2[0]); fma2(ob, qc2[1], S2[1]);
                fma2(oc, qc2[2], S2[2]); fma2(od, qc2[3], S2[3]);
                fma2(oa, qc2[4], S2[4]); fma2(ob, qc2[5], S2[5]);
                fma2(oc, qc2[6], S2[6]); fma2(od, qc2[7], S2[7]);
                add2(oa, oa, ob); add2(oc, oc, od); add2(oa, oa, oc);
                float olo, ohi; up2(oa, olo, ohi);
                float o = olo + ohi;
                o += __shfl_xor_sync(0xffffffffu, o, 1);
                o += __shfl_xor_sync(0xffffffffu, o, 2);
                if (j == 0) op[(size_t)(s >> 1) * ROW] = o;
            }

            if (sp < GSTEPS - 1) {
#pragma unroll
                for (int m = 0; m < 8; m++) kc2[m] = kn2[m];
            }
        }

        CP_WAIT(2);
        __syncthreads();
    }
}

// ---------------------------------------------------------------------------
// Gated RMSNorm + swish gate, in-place on g_obuf. One warp per (t,h) row.
// ---------------------------------------------------------------------------
__global__ void post_kernel(const float* __restrict__ nw)
{
    int w = (blockIdx.x * blockDim.x + threadIdx.x) >> 5;
    int lane = threadIdx.x & 31;
    if (w >= T_ * H_) return;
    float* p = g_obuf + (size_t)w * 64;
    const float* gp = g_gbuf + (size_t)w * 64;
    float x0 = p[lane], x1 = p[lane + 32];
    float ss = x0 * x0 + x1 * x1;
#pragma unroll
    for (int o = 16; o; o >>= 1) ss += __shfl_xor_sync(0xffffffffu, ss, o);
    float rs = rsqrtf(ss * (1.0f / 64.0f) + 1e-5f);
    float g0 = gp[lane], g1 = gp[lane + 32];
    float w0 = nw[lane], w1 = nw[lane + 32];
    float sg0 = g0 / (1.0f + expf(-g0));
    float sg1 = g1 / (1.0f + expf(-g1));
    p[lane]      = x0 * rs * w0 * sg0;
    p[lane + 32] = x1 * rs * w1 * sg1;
}

// ---------------------------------------------------------------------------
// Host launcher
// ---------------------------------------------------------------------------
extern "C" void kernel_launch(void* const* d_in, const int* in_sizes, int n_in,
                              void* d_out, int out_size)
{
    const float* x       = (const float*)d_in[0];
    const float* Wq      = (const float*)d_in[1];
    const float* Wk      = (const float*)d_in[2];
    const float* Wv      = (const float*)d_in[3];
    const float* Wb      = (const float*)d_in[4];
    const float* Wa      = (const float*)d_in[5];
    const float* A_log   = (const float*)d_in[6];
    const float* dt_bias = (const float*)d_in[7];
    const float* Wg      = (const float*)d_in[8];
    const float* nw      = (const float*)d_in[9];
    const float* Wo      = (const float*)d_in[10];
    float* out = (float*)d_out;

    float *qb, *kb, *vb, *gb, *bb, *ab, *ob;
    cudaGetSymbolAddress((void**)&qb, g_qbuf);
    cudaGetSymbolAddress((void**)&kb, g_kbuf);
    cudaGetSymbolAddress((void**)&vb, g_vbuf);
    cudaGetSymbolAddress((void**)&gb, g_gbuf);
    cudaGetSymbolAddress((void**)&bb, g_bbuf);
    cudaGetSymbolAddress((void**)&ab, g_abuf);
    cudaGetSymbolAddress((void**)&ob, g_obuf);

    // Projections (big GEMMs: 128x128 tiles, 256 threads)
    sgemm_big_kernel<<<dim3(1024 / 128, T_ / 128), 256>>>(x, Wq, qb, T_, 1024, D_);
    sgemm_big_kernel<<<dim3(2048 / 128, T_ / 128), 256>>>(x, Wk, kb, T_, 2048, D_);
    sgemm_big_kernel<<<dim3(2048 / 128, T_ / 128), 256>>>(x, Wv, vb, T_, 2048, D_);
    sgemm_big_kernel<<<dim3(1024 / 128, T_ / 128), 256>>>(x, Wg, gb, T_, 1024, D_);
    // Small projections
    sgemm_kernel<<<dim3(1, T_ / BM), 256>>>(x, Wb, bb, T_, 32, D_);
    sgemm_kernel<<<dim3(1, T_ / BM), 256>>>(x, Wa, ab, T_, 16, D_);

    // Pointwise prep
    {
        int warps = T_ * H_ + STEPS * H_;
        prep_norm_kernel<<<(warps + 7) / 8, 256>>>();
        prep_scalar_kernel<<<(STEPS * H_) / 256, 256>>>(A_log, dt_bias);
    }

    // Sequential scan: 32 blocks (2 per head), 128 threads each
    scan_kernel<<<32, 128>>>();

    // Gated RMSNorm + swish
    post_kernel<<<(T_ * H_ + 7) / 8, 256>>>(nw);

    // Output projection
    sgemm_big_kernel<<<dim3(1024 / 128, T_ / 128), 256>>>(ob, Wo, out, T_, 1024, D_);
}

// round 8
// speedup vs baseline: 1.4185x; 1.4185x over previous
#include <cuda_runtime.h>
#include <cuda_bf16.h>
#include <math.h>
#include <stdint.h>

// ---------------------------------------------------------------------------
// Problem dims (fixed)
// ---------------------------------------------------------------------------
#define T_   2048
#define D_   1024
#define H_   16
#define HD_  64
#define NH_  2
#define STEPS (T_*NH_)          // 4096
#define ROW  (H_*HD_)           // 1024
#define SPAD (STEPS + 8)
#define GSTEPS 8
#define NGRP8 (STEPS/GSTEPS)

// ---------------------------------------------------------------------------
// Scratch (static device memory; allocation-free).
// ---------------------------------------------------------------------------
__device__ __align__(256) float g_qbuf[(T_ + 4) * ROW];
__device__ __align__(256) float g_kbuf[SPAD * ROW];
__device__ __align__(256) float g_vbuf[SPAD * ROW];
__device__ __align__(256) float g_gbuf[T_ * ROW];
__device__ __align__(256) float g_bbuf[T_ * (NH_ * H_)];
__device__ __align__(256) float g_abuf[T_ * H_];
__device__ __align__(256) float g_betab[H_ * SPAD];
__device__ __align__(256) float g_decb[H_ * SPAD];
__device__ __align__(256) float g_obuf[T_ * ROW];

// bf16 split buffers (hi/lo), weights transposed to [N][K]
__device__ __align__(256) __nv_bfloat16 g_xh[T_ * D_],    g_xl[T_ * D_];
__device__ __align__(256) __nv_bfloat16 g_oh[T_ * ROW],   g_ol[T_ * ROW];
__device__ __align__(256) __nv_bfloat16 g_wqh[1024 * D_], g_wql[1024 * D_];
__device__ __align__(256) __nv_bfloat16 g_wkh[2048 * D_], g_wkl[2048 * D_];
__device__ __align__(256) __nv_bfloat16 g_wvh[2048 * D_], g_wvl[2048 * D_];
__device__ __align__(256) __nv_bfloat16 g_wgh[1024 * D_], g_wgl[1024 * D_];
__device__ __align__(256) __nv_bfloat16 g_woh[1024 * ROW], g_wol[1024 * ROW];

// ---------------------------------------------------------------------------
// f32x2 packed helpers
// ---------------------------------------------------------------------------
typedef unsigned long long ull;

__device__ __forceinline__ void fma2(ull& d, ull a, ull b) {
    asm("fma.rn.f32x2 %0, %1, %2, %3;" : "=l"(d) : "l"(a), "l"(b), "l"(d));
}
__device__ __forceinline__ void add2(ull& d, ull a, ull b) {
    asm("add.rn.f32x2 %0, %1, %2;" : "=l"(d) : "l"(a), "l"(b));
}
__device__ __forceinline__ ull mul2(ull a, ull b) {
    ull d;
    asm("mul.rn.f32x2 %0, %1, %2;" : "=l"(d) : "l"(a), "l"(b));
    return d;
}
__device__ __forceinline__ ull pk2(float x, float y) {
    ull r;
    asm("mov.b64 %0, {%1, %2};" : "=l"(r)
        : "r"(__float_as_uint(x)), "r"(__float_as_uint(y)));
    return r;
}
__device__ __forceinline__ void up2(ull v, float& lo, float& hi) {
    unsigned a, b;
    asm("mov.b64 {%0, %1}, %2;" : "=r"(a), "=r"(b) : "l"(v));
    lo = __uint_as_float(a); hi = __uint_as_float(b);
}

// ---------------------------------------------------------------------------
// cp.async helpers (16 BYTES per op)
// ---------------------------------------------------------------------------
__device__ __forceinline__ void cpasync16(void* dst, const void* src) {
    unsigned d = (unsigned)__cvta_generic_to_shared(dst);
    asm volatile("cp.async.cg.shared.global [%0], [%1], 16;" :: "r"(d), "l"(src));
}
#define CP_COMMIT() asm volatile("cp.async.commit_group;")
#define CP_WAIT(n)  asm volatile("cp.async.wait_group %0;" :: "n"(n))

__device__ __forceinline__ uint32_t smem_u32(const void* p) {
    uint32_t a;
    asm("{ .reg .u64 t; cvta.to.shared.u64 t, %1; cvt.u32.u64 %0, t; }"
        : "=r"(a) : "l"(p));
    return a;
}

// ---------------------------------------------------------------------------
// warp-MMA primitives (sm_80+ PTX; works on plain sm_103 target)
// ---------------------------------------------------------------------------
__device__ __forceinline__ void ldsm4(uint32_t addr, uint32_t* r) {
    asm volatile("ldmatrix.sync.aligned.m8n8.x4.shared.b16 {%0,%1,%2,%3}, [%4];"
        : "=r"(r[0]), "=r"(r[1]), "=r"(r[2]), "=r"(r[3]) : "r"(addr));
}
__device__ __forceinline__ void mma16816(float* d, const uint32_t* a, const uint32_t* b) {
    asm volatile(
        "mma.sync.aligned.m16n8k16.row.col.f32.bf16.bf16.f32 "
        "{%0,%1,%2,%3}, {%4,%5,%6,%7}, {%8,%9}, {%0,%1,%2,%3};"
        : "+f"(d[0]), "+f"(d[1]), "+f"(d[2]), "+f"(d[3])
        : "r"(a[0]), "r"(a[1]), "r"(a[2]), "r"(a[3]), "r"(b[0]), "r"(b[1]));
}

// ---------------------------------------------------------------------------
// Warp-MMA GEMM: C[M,N] = A[M,K] @ W[K,N] with A [M,K] row-major bf16 hi/lo
// and B pre-transposed [N,K] bf16 hi/lo. 3 split products (hh + hl + lh),
// fp32 accumulators. 128x128 CTA tile, 256 threads = 8 warps (warp 64x32),
// K chunks of 32 double-buffered via cp.async.
// Smem row stride 40 bf16 (80B): ldmatrix rows land on distinct 16B banks.
// ---------------------------------------------------------------------------
#define KC    32
#define AST   40                 // smem row stride (bf16 elems)
#define TILEE (128 * AST)        // 5120 elems = 10240 B
#define MM_SMEM (2 * 4 * TILEE * 2)   // 81920 B

__device__ __forceinline__ void mm_load_tile(
    __nv_bfloat16* dst, const __nv_bfloat16* src, int row0, int K, int k0, int tid)
{
#pragma unroll
    for (int i = 0; i < 2; i++) {
        int c0 = tid + i * 256;
        int r = c0 >> 2, c = c0 & 3;
        cpasync16(dst + r * AST + c * 8, src + (size_t)(row0 + r) * K + k0 + c * 8);
    }
}

__global__ void __launch_bounds__(256) mm_wmma_kernel(
    const __nv_bfloat16* __restrict__ Ah, const __nv_bfloat16* __restrict__ Al,
    const __nv_bfloat16* __restrict__ Bh, const __nv_bfloat16* __restrict__ Bl,
    float* __restrict__ C, int M, int N, int K)
{
    extern __shared__ __nv_bfloat16 sm[];
    const uint32_t sbase = smem_u32(sm);
    const int tid = threadIdx.x;
    const int wid = tid >> 5;
    const int lane = tid & 31;
    const int rowC = blockIdx.y * 128;
    const int colC = blockIdx.x * 128;
    const int wr = wid >> 2;          // 0..1  -> 64 rows
    const int wc = wid & 3;           // 0..3  -> 32 cols
    const int m0w = wr * 64;
    const int n0w = wc * 32;

    // per-lane ldmatrix address components
    const int arow = lane & 15;
    const int akoff = (lane >> 4) << 3;
    const int brow = ((lane >> 4) << 3) + (lane & 7);
    const int bkoff = ((lane >> 3) & 1) << 3;

    float acc[4][4][4];
#pragma unroll
    for (int mf = 0; mf < 4; mf++)
#pragma unroll
        for (int nf = 0; nf < 4; nf++)
#pragma unroll
            for (int i = 0; i < 4; i++) acc[mf][nf][i] = 0.f;

    const int nch = K / KC;

    // prologue: chunk 0 -> buf 0
    mm_load_tile(sm + 0 * TILEE, Ah, rowC, K, 0, tid);
    mm_load_tile(sm + 1 * TILEE, Al, rowC, K, 0, tid);
    mm_load_tile(sm + 2 * TILEE, Bh, colC, K, 0, tid);
    mm_load_tile(sm + 3 * TILEE, Bl, colC, K, 0, tid);
    CP_COMMIT();

    for (int ch = 0; ch < nch; ch++) {
        const int cur = ch & 1;
        const int nxt = cur ^ 1;
        if (ch + 1 < nch) {
            const int k0 = (ch + 1) * KC;
            mm_load_tile(sm + (nxt * 4 + 0) * TILEE, Ah, rowC, K, k0, tid);
            mm_load_tile(sm + (nxt * 4 + 1) * TILEE, Al, rowC, K, k0, tid);
            mm_load_tile(sm + (nxt * 4 + 2) * TILEE, Bh, colC, K, k0, tid);
            mm_load_tile(sm + (nxt * 4 + 3) * TILEE, Bl, colC, K, k0, tid);
        }
        CP_COMMIT();
        CP_WAIT(1);
        __syncthreads();

        const uint32_t aHb = sbase + (cur * 4 + 0) * (TILEE * 2);
        const uint32_t aLb = sbase + (cur * 4 + 1) * (TILEE * 2);
        const uint32_t bHb = sbase + (cur * 4 + 2) * (TILEE * 2);
        const uint32_t bLb = sbase + (cur * 4 + 3) * (TILEE * 2);

#pragma unroll
        for (int ks = 0; ks < 2; ks++) {
            const int k0 = ks * 16;
            uint32_t ah[4][4], al[4][4], bh[4][2], bl[4][2];
#pragma unroll
            for (int mf = 0; mf < 4; mf++) {
                uint32_t off = ((m0w + mf * 16 + arow) * AST + k0 + akoff) * 2;
                ldsm4(aHb + off, ah[mf]);
                ldsm4(aLb + off, al[mf]);
            }
#pragma unroll
            for (int nb = 0; nb < 2; nb++) {
                uint32_t off = ((n0w + nb * 16 + brow) * AST + k0 + bkoff) * 2;
                uint32_t r[4];
                ldsm4(bHb + off, r);
                bh[nb * 2][0] = r[0]; bh[nb * 2][1] = r[1];
                bh[nb * 2 + 1][0] = r[2]; bh[nb * 2 + 1][1] = r[3];
                ldsm4(bLb + off, r);
                bl[nb * 2][0] = r[0]; bl[nb * 2][1] = r[1];
                bl[nb * 2 + 1][0] = r[2]; bl[nb * 2 + 1][1] = r[3];
            }
#pragma unroll
            for (int mf = 0; mf < 4; mf++)
#pragma unroll
                for (int nf = 0; nf < 4; nf++) {
                    mma16816(acc[mf][nf], ah[mf], bh[nf]);
                    mma16816(acc[mf][nf], ah[mf], bl[nf]);
                    mma16816(acc[mf][nf], al[mf], bh[nf]);
                }
        }
        __syncthreads();
    }

    // epilogue: direct stores (c0,c1 = col pair @ row, c2,c3 @ row+8)
    const int er = lane >> 2;
    const int ec = (lane & 3) * 2;
#pragma unroll
    for (int mf = 0; mf < 4; mf++)
#pragma unroll
        for (int nf = 0; nf < 4; nf++) {
            int row = rowC + m0w + mf * 16 + er;
            int col = colC + n0w + nf * 8 + ec;
            *(float2*)(C + (size_t)row * N + col) =
                make_float2(acc[mf][nf][0], acc[mf][nf][1]);
            *(float2*)(C + (size_t)(row + 8) * N + col) =
                make_float2(acc[mf][nf][2], acc[mf][nf][3]);
        }
}

// ---------------------------------------------------------------------------
// Weight transpose + bf16 hi/lo split: in [K,N] fp32 -> out [N,K] bf16 x2
// ---------------------------------------------------------------------------
__global__ void tr_split_kernel(const float* __restrict__ in,
                                __nv_bfloat16* __restrict__ oh,
                                __nv_bfloat16* __restrict__ ol,
                                int K, int N)
{
    __shared__ float t[32][33];
    int n0 = blockIdx.x * 32, k0 = blockIdx.y * 32;
    int tx = threadIdx.x, ty = threadIdx.y;       // 32 x 8
#pragma unroll
    for (int i = 0; i < 32; i += 8)
        t[ty + i][tx] = in[(size_t)(k0 + ty + i) * N + n0 + tx];
    __syncthreads();
#pragma unroll
    for (int i = 0; i < 32; i += 8) {
        float v = t[tx][ty + i];
        __nv_bfloat16 h = __float2bfloat16(v);
        float r = v - __bfloat162float(h);
        size_t o = (size_t)(n0 + ty + i) * K + k0 + tx;
        oh[o] = h;
        ol[o] = __float2bfloat16(r);
    }
}

// elementwise bf16 hi/lo split
__global__ void split_kernel(const float* __restrict__ in,
                             __nv_bfloat16* __restrict__ oh,
                             __nv_bfloat16* __restrict__ ol, int n)
{
    int i = blockIdx.x * blockDim.x + threadIdx.x;
    if (i >= n) return;
    float v = in[i];
    __nv_bfloat16 h = __float2bfloat16(v);
    oh[i] = h;
    ol[i] = __float2bfloat16(v - __bfloat162float(h));
}

// ---------------------------------------------------------------------------
// Small SGEMM (N=16/32): 128x64 tile, BK=16, 256 threads (fp32).
// ---------------------------------------------------------------------------
#define BM 128
#define BN 64
#define BK 16

__global__ void __launch_bounds__(256) sgemm_kernel(
    const float* __restrict__ A, const float* __restrict__ B,
    float* __restrict__ C, int M, int N, int K)
{
    __shared__ float As[BK][BM + 4];
    __shared__ float Bs[BK][BN];

    const int tid = threadIdx.x;
    const int tx = tid & 15;
    const int ty = tid >> 4;
    const int rowC = blockIdx.y * BM;
    const int colC = blockIdx.x * BN;

    const int rowA = tid >> 2;
    const int kA   = (tid & 3) * 4;
    const int rowB = tid >> 4;
    const int colB = (tid & 15) * 4;

    ull acc2[4][4];
#pragma unroll
    for (int r = 0; r < 4; r++)
#pragma unroll
        for (int jj = 0; jj < 4; jj++) acc2[r][jj] = 0ull;

    for (int k0 = 0; k0 < K; k0 += BK) {
#pragma unroll
        for (int r = 0; r < 2; r++) {
            int row = rowA + r * 64;
            float4 a = *(const float4*)(A + (size_t)(rowC + row) * K + k0 + kA);
            As[kA + 0][row] = a.x; As[kA + 1][row] = a.y;
            As[kA + 2][row] = a.z; As[kA + 3][row] = a.w;
        }
        {
            float4 bv = make_float4(0.f, 0.f, 0.f, 0.f);
            if (colC + colB < N)
                bv = *(const float4*)(B + (size_t)(k0 + rowB) * N + colC + colB);
            Bs[rowB][colB + 0] = bv.x; Bs[rowB][colB + 1] = bv.y;
            Bs[rowB][colB + 2] = bv.z; Bs[rowB][colB + 3] = bv.w;
        }
        __syncthreads();

#pragma unroll
        for (int kk = 0; kk < BK; kk++) {
            float4 b0 = *(const float4*)&Bs[kk][tx * 4];
            ull b2[4];
            b2[0] = pk2(b0.x, b0.x); b2[1] = pk2(b0.y, b0.y);
            b2[2] = pk2(b0.z, b0.z); b2[3] = pk2(b0.w, b0.w);
            ull a2[4];
#pragma unroll
            for (int r = 0; r < 4; r++)
                a2[r] = *(const ull*)&As[kk][ty * 8 + 2 * r];
#pragma unroll
            for (int r = 0; r < 4; r++)
#pragma unroll
                for (int jj = 0; jj < 4; jj++)
                    fma2(acc2[r][jj], a2[r], b2[jj]);
        }
        __syncthreads();
    }

    if (colC + tx * 4 < N) {
#pragma unroll
        for (int r = 0; r < 4; r++) {
            float lo[4], hi[4];
#pragma unroll
            for (int jj = 0; jj < 4; jj++) up2(acc2[r][jj], lo[jj], hi[jj]);
            int row0 = rowC + ty * 8 + 2 * r;
            *(float4*)(C + (size_t)row0 * N + colC + tx * 4) =
                make_float4(lo[0], lo[1], lo[2], lo[3]);
            *(float4*)(C + (size_t)(row0 + 1) * N + colC + tx * 4) =
                make_float4(hi[0], hi[1], hi[2], hi[3]);
        }
    }
}

// ---------------------------------------------------------------------------
// l2norm rows of 64 (q: scale by HD^-0.5; k: no scale). One warp per row.
// ---------------------------------------------------------------------------
__global__ void prep_norm_kernel()
{
    const int TQ = T_ * H_;
    const int TK = STEPS * H_;
    int w = (blockIdx.x * blockDim.x + threadIdx.x) >> 5;
    int lane = threadIdx.x & 31;
    if (w >= TQ + TK) return;
    float* p;
    float scl;
    if (w < TQ) { p = g_qbuf + (size_t)w * 64; scl = 0.125f; }
    else        { p = g_kbuf + (size_t)(w - TQ) * 64; scl = 1.0f; }
    float x0 = p[lane], x1 = p[lane + 32];
    float ss = x0 * x0 + x1 * x1;
#pragma unroll
    for (int o = 16; o; o >>= 1) ss += __shfl_xor_sync(0xffffffffu, ss, o);
    float rs = rsqrtf(ss + 1e-6f) * scl;
    p[lane] = x0 * rs;
    p[lane + 32] = x1 * rs;
}

// ---------------------------------------------------------------------------
// beta/dec precompute, written TRANSPOSED [h][s].
// ---------------------------------------------------------------------------
__global__ void prep_scalar_kernel(const float* __restrict__ A_log,
                                   const float* __restrict__ dt_bias)
{
    int i = blockIdx.x * blockDim.x + threadIdx.x;
    if (i >= STEPS * H_) return;
    int h = i & 15;
    int nh = (i >> 4) & 1;
    int t = i >> 5;
    int s = t * 2 + nh;
    float br = g_bbuf[i];
    g_betab[h * SPAD + s] = 2.0f / (1.0f + expf(-br));
    float d = 1.0f;
    if (nh == 0) {
        float a = g_abuf[t * H_ + h] + dt_bias[h];
        float sp = (a > 20.0f) ? a : log1pf(expf(a));
        d = expf(-expf(A_log[h]) * sp);
    }
    g_decb[h * SPAD + s] = d;
}

// ---------------------------------------------------------------------------
// Scan: cp.async smem ring (groups of 8, 4 slots, lookahead 3), f32x2 math.
// ---------------------------------------------------------------------------
__device__ __forceinline__ void scan_prefetch(
    int gi, int tid,
    const float* kg, const float* qg, const float* vg,
    const float* bg, const float* dg,
    float (*sk)[GSTEPS*64], float (*sq)[(GSTEPS/2)*64],
    float (*sv)[GSTEPS*32], float (*sb)[16])
{
    int slot = gi & 3;
    int s0 = gi * GSTEPS; if (s0 > STEPS) s0 = STEPS;
    int t0 = s0 >> 1;
    {
        int si = tid >> 4, off = (tid & 15) * 4;
        cpasync16(&sk[slot][si * 64 + off], kg + (size_t)(s0 + si) * ROW + off);
    }
    if (tid < 64) {
        int ti = tid >> 4, off = (tid & 15) * 4;
        cpasync16(&sq[slot][ti * 64 + off], qg + (size_t)(t0 + ti) * ROW + off);
    } else {
        int c = tid - 64; int si = c >> 3, off = (c & 7) * 4;
        cpasync16(&sv[slot][si * 32 + off], vg + (size_t)(s0 + si) * ROW + off);
    }
    if (tid < 2)      cpasync16(&sb[slot][tid * 4], bg + s0 + tid * 4);
    else if (tid < 4) cpasync16(&sb[slot][8 + (tid - 2) * 4], dg + s0 + (tid - 2) * 4);
}

__device__ __forceinline__ void lds8u(const float* p, ull* u)
{
    const ull* up = (const ull*)p;
#pragma unroll
    for (int i = 0; i < 8; i++) u[i] = up[i];
}

__global__ void __launch_bounds__(128) scan_kernel()
{
    __shared__ float sk[4][GSTEPS*64];
    __shared__ float sq[4][(GSTEPS/2)*64];
    __shared__ float sv[4][GSTEPS*32];
    __shared__ float sb[4][16];

    const int h = blockIdx.x >> 1;
    const int half = blockIdx.x & 1;
    const int tid = threadIdx.x;
    const int vloc = tid >> 2;
    const int j = tid & 3;
    const int v = (half << 5) + vloc;

    const float* kg = g_kbuf + h * 64;
    const float* qg = g_qbuf + h * 64;
    const float* vg = g_vbuf + h * 64 + half * 32;
    const float* bg = g_betab + h * SPAD;
    const float* dg = g_decb + h * SPAD;
    float* op = g_obuf + h * 64 + v;

    ull S2[8];
#pragma unroll
    for (int m = 0; m < 8; m++) S2[m] = 0ull;

    scan_prefetch(0, tid, kg, qg, vg, bg, dg, sk, sq, sv, sb); CP_COMMIT();
    scan_prefetch(1, tid, kg, qg, vg, bg, dg, sk, sq, sv, sb); CP_COMMIT();
    scan_prefetch(2, tid, kg, qg, vg, bg, dg, sk, sq, sv, sb); CP_COMMIT();
    CP_WAIT(2);
    __syncthreads();

    for (int g = 0; g < NGRP8; g++) {
        scan_prefetch(g + 3, tid, kg, qg, vg, bg, dg, sk, sq, sv, sb);
        CP_COMMIT();

        const int slot = g & 3;
        ull kc2[8], qc2[8];
        lds8u(&sk[slot][j * 16], kc2);

#pragma unroll
        for (int sp = 0; sp < GSTEPS; sp++) {
            const int s = g * GSTEPS + sp;
            ull kn2[8];
            if (sp < GSTEPS - 1) lds8u(&sk[slot][(sp + 1) * 64 + j * 16], kn2);
            if (!(sp & 1)) lds8u(&sq[slot][(sp >> 1) * 64 + j * 16], qc2);

            float vv = sv[slot][sp * 32 + vloc];
            float bb = sb[slot][sp];
            float dd = sb[slot][8 + sp];

            ull pa = 0ull, pb = 0ull, pc = 0ull, pd = 0ull;
            fma2(pa, kc2[0], S2[0]); fma2(pb, kc2[1], S2[1]);
            fma2(pc, kc2[2], S2[2]); fma2(pd, kc2[3], S2[3]);
            fma2(pa, kc2[4], S2[4]); fma2(pb, kc2[5], S2[5]);
            fma2(pc, kc2[6], S2[6]); fma2(pd, kc2[7], S2[7]);
            add2(pa, pa, pb); add2(pc, pc, pd); add2(pa, pa, pc);
            float plo, phi; up2(pa, plo, phi);
            float pred = plo + phi;
            pred += __shfl_xor_sync(0xffffffffu, pred, 1);
            pred += __shfl_xor_sync(0xffffffffu, pred, 2);

            float dv = (vv - dd * pred) * bb;
            ull dd2 = pk2(dd, dd);
            ull dv2 = pk2(dv, dv);
#pragma unroll
            for (int m = 0; m < 8; m++) {
                ull t = mul2(kc2[m], dv2);
                fma2(t, S2[m], dd2);
                S2[m] = t;
            }

            if (sp & 1) {
                ull oa = 0ull, ob = 0ull, oc = 0ull, od = 0ull;
                fma2(oa, qc2[0], S2[0]); fma2(ob, qc2[1], S2[1]);
                fma2(oc, qc2[2], S2[2]); fma2(od, qc2[3], S2[3]);
                fma2(oa, qc2[4], S2[4]); fma2(ob, qc2[5], S2[5]);
                fma2(oc, qc2[6], S2[6]); fma2(od, qc2[7], S2[7]);
                add2(oa, oa, ob); add2(oc, oc, od); add2(oa, oa, oc);
                float olo, ohi; up2(oa, olo, ohi);
                float o = olo + ohi;
                o += __shfl_xor_sync(0xffffffffu, o, 1);
                o += __shfl_xor_sync(0xffffffffu, o, 2);
                if (j == 0) op[(size_t)(s >> 1) * ROW] = o;
            }

            if (sp < GSTEPS - 1) {
#pragma unroll
                for (int m = 0; m < 8; m++) kc2[m] = kn2[m];
            }
        }

        CP_WAIT(2);
        __syncthreads();
    }
}

// ---------------------------------------------------------------------------
// Gated RMSNorm + swish gate, in-place on g_obuf. One warp per (t,h) row.
// ---------------------------------------------------------------------------
__global__ void post_kernel(const float* __restrict__ nw)
{
    int w = (blockIdx.x * blockDim.x + threadIdx.x) >> 5;
    int lane = threadIdx.x & 31;
    if (w >= T_ * H_) return;
    float* p = g_obuf + (size_t)w * 64;
    const float* gp = g_gbuf + (size_t)w * 64;
    float x0 = p[lane], x1 = p[lane + 32];
    float ss = x0 * x0 + x1 * x1;
#pragma unroll
    for (int o = 16; o; o >>= 1) ss += __shfl_xor_sync(0xffffffffu, ss, o);
    float rs = rsqrtf(ss * (1.0f / 64.0f) + 1e-5f);
    float g0 = gp[lane], g1 = gp[lane + 32];
    float w0 = nw[lane], w1 = nw[lane + 32];
    float sg0 = g0 / (1.0f + expf(-g0));
    float sg1 = g1 / (1.0f + expf(-g1));
    p[lane]      = x0 * rs * w0 * sg0;
    p[lane + 32] = x1 * rs * w1 * sg1;
}

// ---------------------------------------------------------------------------
// Host launcher
// ---------------------------------------------------------------------------
extern "C" void kernel_launch(void* const* d_in, const int* in_sizes, int n_in,
                              void* d_out, int out_size)
{
    const float* x       = (const float*)d_in[0];
    const float* Wq      = (const float*)d_in[1];
    const float* Wk      = (const float*)d_in[2];
    const float* Wv      = (const float*)d_in[3];
    const float* Wb      = (const float*)d_in[4];
    const float* Wa      = (const float*)d_in[5];
    const float* A_log   = (const float*)d_in[6];
    const float* dt_bias = (const float*)d_in[7];
    const float* Wg      = (const float*)d_in[8];
    const float* nw      = (const float*)d_in[9];
    const float* Wo      = (const float*)d_in[10];
    float* out = (float*)d_out;

    cudaFuncSetAttribute(mm_wmma_kernel,
        cudaFuncAttributeMaxDynamicSharedMemorySize, MM_SMEM);

    float *qb, *kb, *vb, *gb, *bb, *ab, *ob;
    cudaGetSymbolAddress((void**)&qb, g_qbuf);
    cudaGetSymbolAddress((void**)&kb, g_kbuf);
    cudaGetSymbolAddress((void**)&vb, g_vbuf);
    cudaGetSymbolAddress((void**)&gb, g_gbuf);
    cudaGetSymbolAddress((void**)&bb, g_bbuf);
    cudaGetSymbolAddress((void**)&ab, g_abuf);
    cudaGetSymbolAddress((void**)&ob, g_obuf);

    __nv_bfloat16 *xh, *xl, *oh, *ol;
    __nv_bfloat16 *wqh, *wql, *wkh, *wkl, *wvh, *wvl, *wgh, *wgl, *woh, *wol;
    cudaGetSymbolAddress((void**)&xh, g_xh);   cudaGetSymbolAddress((void**)&xl, g_xl);
    cudaGetSymbolAddress((void**)&oh, g_oh);   cudaGetSymbolAddress((void**)&ol, g_ol);
    cudaGetSymbolAddress((void**)&wqh, g_wqh); cudaGetSymbolAddress((void**)&wql, g_wql);
    cudaGetSymbolAddress((void**)&wkh, g_wkh); cudaGetSymbolAddress((void**)&wkl, g_wkl);
    cudaGetSymbolAddress((void**)&wvh, g_wvh); cudaGetSymbolAddress((void**)&wvl, g_wvl);
    cudaGetSymbolAddress((void**)&wgh, g_wgh); cudaGetSymbolAddress((void**)&wgl, g_wgl);
    cudaGetSymbolAddress((void**)&woh, g_woh); cudaGetSymbolAddress((void**)&wol, g_wol);

    dim3 trb(32, 8);
    // transpose + split weights to [N,K] bf16 hi/lo
    tr_split_kernel<<<dim3(1024/32, 1024/32), trb>>>(Wq, wqh, wql, D_, 1024);
    tr_split_kernel<<<dim3(2048/32, 1024/32), trb>>>(Wk, wkh, wkl, D_, 2048);
    tr_split_kernel<<<dim3(2048/32, 1024/32), trb>>>(Wv, wvh, wvl, D_, 2048);
    tr_split_kernel<<<dim3(1024/32, 1024/32), trb>>>(Wg, wgh, wgl, D_, 1024);
    tr_split_kernel<<<dim3(1024/32, 1024/32), trb>>>(Wo, woh, wol, ROW, 1024);
    // split x
    split_kernel<<<(T_ * D_) / 256, 256>>>(x, xh, xl, T_ * D_);

    // tensor-core projections (warp MMA)
    mm_wmma_kernel<<<dim3(1024/128, T_/128), 256, MM_SMEM>>>(xh, xl, wqh, wql, qb, T_, 1024, D_);
    mm_wmma_kernel<<<dim3(2048/128, T_/128), 256, MM_SMEM>>>(xh, xl, wkh, wkl, kb, T_, 2048, D_);
    mm_wmma_kernel<<<dim3(2048/128, T_/128), 256, MM_SMEM>>>(xh, xl, wvh, wvl, vb, T_, 2048, D_);
    mm_wmma_kernel<<<dim3(1024/128, T_/128), 256, MM_SMEM>>>(xh, xl, wgh, wgl, gb, T_, 1024, D_);
    // small projections (fp32 SIMT)
    sgemm_kernel<<<dim3(1, T_ / BM), 256>>>(x, Wb, bb, T_, 32, D_);
    sgemm_kernel<<<dim3(1, T_ / BM), 256>>>(x, Wa, ab, T_, 16, D_);

    // pointwise prep
    {
        int warps = T_ * H_ + STEPS * H_;
        prep_norm_kernel<<<(warps + 7) / 8, 256>>>();
        prep_scalar_kernel<<<(STEPS * H_) / 256, 256>>>(A_log, dt_bias);
    }

    // sequential scan
    scan_kernel<<<32, 128>>>();

    // gated RMSNorm + swish
    post_kernel<<<(T_ * H_ + 7) / 8, 256>>>(nw);

    // output projection (warp MMA)
    split_kernel<<<(T_ * ROW) / 256, 256>>>(ob, oh, ol, T_ * ROW);
    mm_wmma_kernel<<<dim3(1024/128, T_/128), 256, MM_SMEM>>>(oh, ol, woh, wol, out, T_, 1024, ROW);
}